// round 10
// baseline (speedup 1.0000x reference)
#include <cuda_runtime.h>
#include <cuda_bf16.h>

#define NAG  4096
#define H    64
#define CAP  128
#define NBLK 128
#define NTHR 512

// ---------------- device scratch (no allocations allowed) ----------------
__device__ int   g_cnt[NAG];
__device__ int   g_list[NAG * CAP];
__device__ float g_x[NAG * H];     // embedding output (residual)
__device__ float g_h[NAG * H];     // layer io
__device__ float g_hw[NAG * H];    // h @ W
__device__ float g_ssrc[NAG];
__device__ float g_sdst[NAG];
__device__ float g_part[NBLK];
__device__ unsigned          g_bar_cnt = 0;
__device__ volatile unsigned g_bar_gen = 0;

// ---------------- grid-wide barrier (all 128 blocks resident) ------------
__device__ __forceinline__ void grid_sync() {
    __syncthreads();
    if (threadIdx.x == 0) {
        unsigned gen = g_bar_gen;
        __threadfence();
        if (atomicAdd(&g_bar_cnt, 1u) == NBLK - 1) {
            g_bar_cnt = 0;
            __threadfence();
            g_bar_gen = gen + 1;
        } else {
            while (g_bar_gen == gen) { }
        }
        __threadfence();
    }
    __syncthreads();
}

// ---------------- shared memory union ------------------------------------
struct SMem {
    union {
        struct { float W[64 * 64]; float In[32 * 64]; } g;   // 24 KB (gemm/emb)
        struct { float w[16][CAP]; int j[16][CAP]; } a;      // 16 KB (agg)
        float red[NBLK];                                     // reductions
    };
};

__device__ __forceinline__ float decode_ts(const void* p) {
    int iv = *(const int*)p;
    if (iv > -1000000 && iv < 1000000) return (float)iv;  // int32 timestep
    return __int_as_float(iv);                            // float32 timestep
}

// GEMM (32 rows/block) + fused attention scores.
// thread = (r = tid>>4, c = tid&15): computes row r, cols 4c..4c+3.
// Per k: 1 broadcast scalar LDS (input) + 1 LDS.128 (W) -> 4 FMA.
__device__ __forceinline__ void gemm_scores_phase(
        SMem* sm, const float* __restrict__ in, const float* __restrict__ W,
        const float* __restrict__ asrc, const float* __restrict__ adst) {
    int tid = threadIdx.x;
    int r0 = blockIdx.x * 32;
    float4* shW4 = (float4*)sm->g.W;
    shW4[tid]       = ((const float4*)W)[tid];
    shW4[tid + 512] = ((const float4*)W)[tid + 512];
    ((float4*)sm->g.In)[tid] = ((const float4*)(in + r0 * 64))[tid];
    __syncthreads();
    int r = tid >> 4, c = tid & 15;
    const float* shIn = sm->g.In;
    float4 acc = make_float4(0.f, 0.f, 0.f, 0.f);
#pragma unroll
    for (int k = 0; k < 64; k++) {
        float iv = shIn[r * 64 + k];
        float4 wv = shW4[k * 16 + c];
        acc.x += iv * wv.x; acc.y += iv * wv.y;
        acc.z += iv * wv.z; acc.w += iv * wv.w;
    }
    ((float4*)g_hw)[(r0 + r) * 16 + c] = acc;
    float4 as = ((const float4*)asrc)[c];
    float4 ad = ((const float4*)adst)[c];
    float ps = acc.x * as.x + acc.y * as.y + acc.z * as.z + acc.w * as.w;
    float pd = acc.x * ad.x + acc.y * ad.y + acc.z * ad.z + acc.w * ad.w;
#pragma unroll
    for (int off = 8; off; off >>= 1) {
        ps += __shfl_xor_sync(0xFFFFFFFFu, ps, off, 16);
        pd += __shfl_xor_sync(0xFFFFFFFFu, pd, off, 16);
    }
    if (c == 0) { g_ssrc[r0 + r] = ps; g_sdst[r0 + r] = pd; }
}

// Aggregation: softmax over neighbors + weighted sum. 16 warps x 2 rows.
__device__ __forceinline__ void agg_phase(SMem* sm,
        const float* __restrict__ bias, int dorelu) {
    int tid = threadIdx.x;
    int lane = tid & 31, w = tid >> 5;
    float* shw = sm->a.w[w];
    int*   shj = sm->a.j[w];
    const float2* __restrict__ hw2 = (const float2*)g_hw;
    float2 bb = ((const float2*)bias)[lane];
#pragma unroll 1
    for (int rr = 0; rr < 2; rr++) {
        int row = blockIdx.x * 32 + w * 2 + rr;
        int deg = min(g_cnt[row], CAP);
        float sd = g_sdst[row];
        for (int n = lane; n < deg; n += 32) {
            int j = g_list[row * CAP + n];
            float e = g_ssrc[j] + sd;
            e = (e >= 0.f) ? e : 0.2f * e;
            shw[n] = e;
            shj[n] = j;
        }
        float es = g_ssrc[row] + sd;            // self-loop
        es = (es >= 0.f) ? es : 0.2f * es;
        __syncwarp();
        float m = es;
        for (int n = lane; n < deg; n += 32) m = fmaxf(m, shw[n]);
#pragma unroll
        for (int off = 16; off; off >>= 1)
            m = fmaxf(m, __shfl_xor_sync(0xFFFFFFFFu, m, off));
        float part = 0.f;
        for (int n = lane; n < deg; n += 32) {
            float ww = expf(shw[n] - m);
            shw[n] = ww;
            part += ww;
        }
#pragma unroll
        for (int off = 16; off; off >>= 1)
            part += __shfl_xor_sync(0xFFFFFFFFu, part, off);
        float wself = expf(es - m);
        float denom = part + wself;
        __syncwarp();
        float2 vself = hw2[row * 32 + lane];
        float2 accA = make_float2(wself * vself.x, wself * vself.y);
        float2 accB = make_float2(0.f, 0.f);
        int n = 0;
        for (; n + 4 <= deg; n += 4) {
            float w0 = shw[n + 0], w1 = shw[n + 1];
            float w2 = shw[n + 2], w3 = shw[n + 3];
            int j0 = shj[n + 0], j1 = shj[n + 1];
            int j2 = shj[n + 2], j3 = shj[n + 3];
            float2 v0 = hw2[j0 * 32 + lane];
            float2 v1 = hw2[j1 * 32 + lane];
            float2 v2 = hw2[j2 * 32 + lane];
            float2 v3 = hw2[j3 * 32 + lane];
            accA.x += w0 * v0.x; accA.y += w0 * v0.y;
            accB.x += w1 * v1.x; accB.y += w1 * v1.y;
            accA.x += w2 * v2.x; accA.y += w2 * v2.y;
            accB.x += w3 * v3.x; accB.y += w3 * v3.y;
        }
        for (; n < deg; n++) {
            float ww = shw[n];
            float2 v = hw2[shj[n] * 32 + lane];
            accA.x += ww * v.x; accA.y += ww * v.y;
        }
        float inv = 1.f / denom;
        float o0 = (accA.x + accB.x) * inv + bb.x;
        float o1 = (accA.y + accB.y) * inv + bb.y;
        if (dorelu) { o0 = fmaxf(o0, 0.f); o1 = fmaxf(o1, 0.f); }
        ((float2*)g_h)[row * 32 + lane] = make_float2(o0, o1);
        __syncwarp();   // buffer reuse between rr iterations
    }
}

// ---------------- the whole model in one persistent kernel ---------------
__global__ void __launch_bounds__(NTHR)
PairedKidneyCritic_all(
        const float4* __restrict__ adj4, const void* __restrict__ tsp,
        const float* __restrict__ arr, const float* __restrict__ dep,
        const float* __restrict__ hard,
        const float* __restrict__ emb_w1, const float* __restrict__ emb_b1,
        const float* __restrict__ emb_w2, const float* __restrict__ emb_b2,
        const float* __restrict__ gat_w, const float* __restrict__ gat_as,
        const float* __restrict__ gat_ad, const float* __restrict__ gat_b,
        const float* __restrict__ val_w, const float* __restrict__ val_b,
        float* __restrict__ out) {
    __shared__ SMem sm;
    int tid = threadIdx.x;
    int bid = blockIdx.x;

    // ---- phase 0: zero neighbor counts ----
    if (tid < 32) g_cnt[bid * 32 + tid] = 0;
    grid_sync();

    // ---- phase 1a: embedding (32 rows/block) ----
    {
        int r0 = bid * 32;
        float4* shW4 = (float4*)sm.g.W;
        shW4[tid]       = ((const float4*)emb_w2)[tid];
        shW4[tid + 512] = ((const float4*)emb_w2)[tid + 512];
        float ts = decode_ts(tsp);
        int r = tid >> 4, c = tid & 15;
        int row = r0 + r;
        float a = arr[row];
        float pg = (ts - a) / (dep[row] - a);
        float q = hard[row];
        float4 w1a = ((const float4*)emb_w1)[c];
        float4 w1b = ((const float4*)(emb_w1 + 64))[c];
        float4 b1v = ((const float4*)emb_b1)[c];
        float4 t4;
        t4.x = pg * w1a.x + q * w1b.x + b1v.x;
        t4.y = pg * w1a.y + q * w1b.y + b1v.y;
        t4.z = pg * w1a.z + q * w1b.z + b1v.z;
        t4.w = pg * w1a.w + q * w1b.w + b1v.w;
        ((float4*)sm.g.In)[r * 16 + c] = t4;
        __syncthreads();
        const float* shT = sm.g.In;
        float4 acc = make_float4(0.f, 0.f, 0.f, 0.f);
#pragma unroll
        for (int k = 0; k < 64; k++) {
            float iv = shT[r * 64 + k];
            float4 wv = shW4[k * 16 + c];
            acc.x += iv * wv.x; acc.y += iv * wv.y;
            acc.z += iv * wv.z; acc.w += iv * wv.w;
        }
        float4 b2v = ((const float4*)emb_b2)[c];
        acc.x += b2v.x; acc.y += b2v.y; acc.z += b2v.z; acc.w += b2v.w;
        ((float4*)g_x)[row * 16 + c] = acc;
    }

    // ---- phase 1b: adjacency sweep -> neighbor lists ----
    // mask[i][j] = adj[j][i] != 0 (self-loop added once in aggregation).
    {
        int gt = bid * NTHR + tid;
#pragma unroll 1
        for (int s = 0; s < 64; s += 4) {
            float4 v[4];
#pragma unroll
            for (int q = 0; q < 4; q++) v[q] = adj4[gt + (s + q) * 65536];
#pragma unroll
            for (int q = 0; q < 4; q++) {
                int i = gt + (s + q) * 65536;
                int j  = i >> 10;              // source row of adjacency
                int c0 = (i & 1023) << 2;      // destination column base
                float vv[4] = {v[q].x, v[q].y, v[q].z, v[q].w};
#pragma unroll
                for (int t = 0; t < 4; t++) {
                    int dst = c0 + t;
                    if (vv[t] != 0.0f && dst != j) {
                        int slot = atomicAdd(&g_cnt[dst], 1);
                        if (slot < CAP) g_list[dst * CAP + slot] = j;
                    }
                }
            }
        }
    }
    grid_sync();

    // ---- GAT layers ----
#pragma unroll 1
    for (int l = 0; l < 3; l++) {
        gemm_scores_phase(&sm, l == 0 ? g_x : g_h, gat_w + l * H * H,
                          gat_as + l * H, gat_ad + l * H);
        grid_sync();
        agg_phase(&sm, gat_b + l * H, l < 2 ? 1 : 0);
        grid_sync();
    }

    // ---- epilogue: residual + layernorm + dot(val_w), per-block partial ----
    {
        int lane = tid & 31, w = tid >> 5;
        float vw0 = val_w[lane], vw1 = val_w[32 + lane];
#pragma unroll 1
        for (int rr = 0; rr < 2; rr++) {
            int row = bid * 32 + w * 2 + rr;
            float z0 = g_x[row * 64 + lane] + g_h[row * 64 + lane];
            float z1 = g_x[row * 64 + 32 + lane] + g_h[row * 64 + 32 + lane];
            float s = z0 + z1;
#pragma unroll
            for (int off = 16; off; off >>= 1)
                s += __shfl_xor_sync(0xFFFFFFFFu, s, off);
            float mu = s * (1.0f / 64.0f);
            float d0 = z0 - mu, d1 = z1 - mu;
            float v = d0 * d0 + d1 * d1;
#pragma unroll
            for (int off = 16; off; off >>= 1)
                v += __shfl_xor_sync(0xFFFFFFFFu, v, off);
            float inv = 1.0f / sqrtf(v * (1.0f / 64.0f) + 1e-5f);
            float p = (d0 * inv) * vw0 + (d1 * inv) * vw1;
#pragma unroll
            for (int off = 16; off; off >>= 1)
                p += __shfl_xor_sync(0xFFFFFFFFu, p, off);
            if (lane == 0) sm.red[w * 2 + rr] = p;
        }
        __syncthreads();
        if (tid == 0) {
            float bp = 0.f;
#pragma unroll
            for (int k = 0; k < 32; k++) bp += sm.red[k];   // fixed order
            g_part[bid] = bp;
        }
    }
    grid_sync();

    // ---- final: block 0 reduces 128 partials, relu, write ----
    if (bid == 0) {
        if (tid < NBLK) sm.red[tid] = g_part[tid];
        __syncthreads();
#pragma unroll
        for (int st = 64; st; st >>= 1) {
            if (tid < st) sm.red[tid] += sm.red[tid + st];
            __syncthreads();
        }
        if (tid == 0) {
            float r = sm.red[0] * (1.0f / 4096.0f) + val_b[0];
            out[0] = fmaxf(r, 0.f);
        }
    }
}

// ---------------- launch ----------------
extern "C" void kernel_launch(void* const* d_in, const int* in_sizes, int n_in,
                              void* d_out, int out_size) {
    const float* adj    = (const float*)d_in[0];
    const void*  tsp    = d_in[1];
    const float* arr    = (const float*)d_in[2];
    const float* dep    = (const float*)d_in[3];
    const float* hard   = (const float*)d_in[4];
    // d_in[5] = active_agents (all ones, unused by the reference math)
    const float* emb_w1 = (const float*)d_in[6];
    const float* emb_b1 = (const float*)d_in[7];
    const float* emb_w2 = (const float*)d_in[8];
    const float* emb_b2 = (const float*)d_in[9];
    const float* gat_w  = (const float*)d_in[10];
    const float* gat_as = (const float*)d_in[11];
    const float* gat_ad = (const float*)d_in[12];
    const float* gat_b  = (const float*)d_in[13];
    const float* val_w  = (const float*)d_in[14];
    const float* val_b  = (const float*)d_in[15];
    float* out = (float*)d_out;

    PairedKidneyCritic_all<<<NBLK, NTHR>>>(
        (const float4*)adj, tsp, arr, dep, hard,
        emb_w1, emb_b1, emb_w2, emb_b2,
        gat_w, gat_as, gat_ad, gat_b, val_w, val_b, out);
}